// round 4
// baseline (speedup 1.0000x reference)
#include <cuda_runtime.h>
#include <cuda_bf16.h>
#include <cstdint>
#include <cstddef>
#include <math.h>

// Problem constants
#define BATCH 768
#define UNITS 256
#define DHID  1024
#define GROUPS 8
#define J1N   96              // BATCH / GROUPS
#define BATCH2 1536           // 2 * BATCH (key rows then query rows)
#define W_ELEMS 150994944ll   // 768*768*256

// ---------------- device scratch (no allocations allowed) ----------------
__device__ float g_H[BATCH2 * DHID];          // hidden activations (leaky), 6.3MB
__device__ float g_part[4 * BATCH2 * UNITS];  // split-K partials for GEMM2
__device__ float g_Ek [BATCH * UNITS];        // exp(key*t)
__device__ float g_iEk[BATCH * UNITS];        // 1/exp(key*t)
__device__ float g_Eq [BATCH * UNITS];        // exp(query*t)
__device__ float g_iEq[BATCH * UNITS];        // 1/exp(query*t)
__device__ int   g_mask_mode;                 // 0=f32, 1=bf16, 2=i32, 3=u8

__device__ __forceinline__ bool mask_at(const void* m, int mode, int idx) {
    switch (mode) {
        case 0:  return ((const float*)m)[idx] != 0.0f;
        case 1:  return ((const unsigned short*)m)[idx] != 0;
        case 2:  return ((const int*)m)[idx] != 0;
        default: return ((const unsigned char*)m)[idx] != 0;
    }
}

// packed f32x2 FMA: d = a*b + d  (FFMA2, PTX-only on sm_103a)
#define FMA2(c, a, b) \
    asm("fma.rn.f32x2 %0, %1, %2, %0;" : "+l"(c) : "l"(a), "l"(b))

__device__ __forceinline__ void unpack2(uint64_t v, float& lo, float& hi) {
    asm("mov.b64 {%0, %1}, %2;" : "=f"(lo), "=f"(hi) : "l"(v));
}

// ---------------- standalone mask dtype detection (tail path only) -------
__global__ void k_detect_mask(const unsigned char* __restrict__ m) {
    __shared__ int ok[4];
    if (threadIdx.x < 4) ok[threadIdx.x] = 1;
    __syncthreads();
    const unsigned int* w = (const unsigned int*)m;
    for (int idx = threadIdx.x; idx < 256; idx += blockDim.x) {
        unsigned int v = w[idx];
        if (!(v == 0u || v == 0x3F800000u)) atomicAnd(&ok[0], 0);
        unsigned int h0 = v & 0xFFFFu, h1 = v >> 16;
        if (!((h0 == 0u || h0 == 0x3F80u) && (h1 == 0u || h1 == 0x3F80u)))
            atomicAnd(&ok[1], 0);
        if (v > 1u) atomicAnd(&ok[2], 0);
        if ((v & 0xFEFEFEFEu) != 0u) atomicAnd(&ok[3], 0);
    }
    __syncthreads();
    if (threadIdx.x == 0)
        g_mask_mode = ok[0] ? 0 : (ok[1] ? 1 : (ok[2] ? 2 : 3));
}

// ---------------- GEMM tiles: 128x64x16, 256 threads, f32x2 FMA ----------
#define GBM 128
#define GBN 64
#define GBK 16

// GEMM1: H[1536,1024] = leaky(X2[1536,256] @ W1 + b1)
// X2 rows 0..767 = x, rows 768..1535 = x with mask applied (masked -> 0).
__global__ __launch_bounds__(256) void k_gemm1(
    const float* __restrict__ x, const void* __restrict__ mask,
    const float* __restrict__ W1, const float* __restrict__ b1)
{
    __shared__ float As[GBK][GBM];
    __shared__ float Bs2[GBK][2 * GBN];
    const int tid = threadIdx.x;

    // inline mask dtype detection (uniform result, 4 cheap barriers)
    {
        unsigned int v = ((const unsigned int*)mask)[tid];
        unsigned int h0 = v & 0xFFFFu, h1 = v >> 16;
        int m_f32 = __syncthreads_and((v == 0u) || (v == 0x3F800000u));
        int m_bf  = __syncthreads_and((h0 == 0u || h0 == 0x3F80u) &&
                                      (h1 == 0u || h1 == 0x3F80u));
        int m_i32 = __syncthreads_and(v <= 1u);
        g_mask_mode = m_f32 ? 0 : (m_bf ? 1 : (m_i32 ? 2 : 3));
        // NOTE: write races across blocks but all write the same value.
    }
    const int mmode = g_mask_mode;

    const int bn = blockIdx.x;            // 0..15
    const int bm = blockIdx.y;            // 0..11
    const int tx = tid & 15, ty = tid >> 4;
    const int row0 = bm * GBM, col0 = bn * GBN;

    const int am  = tid >> 2;             // 0..63
    const int akq = (tid & 3) * 4;        // 0,4,8,12
    const int bk_ = tid >> 4;             // 0..15
    const int bnq = (tid & 15) * 4;       // n quad

    uint64_t acc[4][4];
#pragma unroll
    for (int r = 0; r < 4; r++)
#pragma unroll
        for (int c = 0; c < 4; c++) acc[r][c] = 0ull;

    for (int k0 = 0; k0 < UNITS; k0 += GBK) {
        // A tile: 128 rows x 16 k. Each thread: 2 float4 (rows am, am+64).
#pragma unroll
        for (int rr = 0; rr < 2; rr++) {
            int m = am + rr * 64;
            int gr = row0 + m;
            float4 av;
            if (gr < BATCH) {
                av = *(const float4*)(x + (size_t)gr * UNITS + k0 + akq);
            } else {
                int base = (gr - BATCH) * UNITS + k0 + akq;
                av = *(const float4*)(x + base);
                if (mask_at(mask, mmode, base + 0)) av.x = 0.f;
                if (mask_at(mask, mmode, base + 1)) av.y = 0.f;
                if (mask_at(mask, mmode, base + 2)) av.z = 0.f;
                if (mask_at(mask, mmode, base + 3)) av.w = 0.f;
            }
            As[akq + 0][m] = av.x; As[akq + 1][m] = av.y;
            As[akq + 2][m] = av.z; As[akq + 3][m] = av.w;
        }
        // B tile, duplicated pairs: Bs2[k][2c]=Bs2[k][2c+1]=B[k][c]
        {
            float4 bv = *(const float4*)(W1 + (size_t)(k0 + bk_) * DHID + col0 + bnq);
            float2* bp = (float2*)&Bs2[bk_][2 * bnq];
            bp[0] = make_float2(bv.x, bv.x);
            bp[1] = make_float2(bv.y, bv.y);
            bp[2] = make_float2(bv.z, bv.z);
            bp[3] = make_float2(bv.w, bv.w);
        }
        __syncthreads();
#pragma unroll
        for (int kk = 0; kk < GBK; kk++) {
            ulonglong2 a01 = *(const ulonglong2*)&As[kk][ty * 8];
            ulonglong2 a23 = *(const ulonglong2*)&As[kk][ty * 8 + 4];
            ulonglong2 b01 = *(const ulonglong2*)&Bs2[kk][tx * 8];
            ulonglong2 b23 = *(const ulonglong2*)&Bs2[kk][tx * 8 + 4];
            FMA2(acc[0][0], a01.x, b01.x); FMA2(acc[0][1], a01.x, b01.y);
            FMA2(acc[0][2], a01.x, b23.x); FMA2(acc[0][3], a01.x, b23.y);
            FMA2(acc[1][0], a01.y, b01.x); FMA2(acc[1][1], a01.y, b01.y);
            FMA2(acc[1][2], a01.y, b23.x); FMA2(acc[1][3], a01.y, b23.y);
            FMA2(acc[2][0], a23.x, b01.x); FMA2(acc[2][1], a23.x, b01.y);
            FMA2(acc[2][2], a23.x, b23.x); FMA2(acc[2][3], a23.x, b23.y);
            FMA2(acc[3][0], a23.y, b01.x); FMA2(acc[3][1], a23.y, b01.y);
            FMA2(acc[3][2], a23.y, b23.x); FMA2(acc[3][3], a23.y, b23.y);
        }
        __syncthreads();
    }
    // epilogue: + b1, leaky_relu(0.01), store H. acc[rp][c] = rows (r0+2rp, r0+2rp+1)
    float4 bb = *(const float4*)(b1 + col0 + tx * 4);
    float bias[4] = {bb.x, bb.y, bb.z, bb.w};
    const int r0 = ty * 8;
#pragma unroll
    for (int rp = 0; rp < 4; rp++) {
        float lo[4], hi[4];
#pragma unroll
        for (int c = 0; c < 4; c++) unpack2(acc[rp][c], lo[c], hi[c]);
        int grl = row0 + r0 + rp * 2;
        float4 olo, ohi;
        float v;
        v = lo[0] + bias[0]; olo.x = v > 0.f ? v : 0.01f * v;
        v = lo[1] + bias[1]; olo.y = v > 0.f ? v : 0.01f * v;
        v = lo[2] + bias[2]; olo.z = v > 0.f ? v : 0.01f * v;
        v = lo[3] + bias[3]; olo.w = v > 0.f ? v : 0.01f * v;
        v = hi[0] + bias[0]; ohi.x = v > 0.f ? v : 0.01f * v;
        v = hi[1] + bias[1]; ohi.y = v > 0.f ? v : 0.01f * v;
        v = hi[2] + bias[2]; ohi.z = v > 0.f ? v : 0.01f * v;
        v = hi[3] + bias[3]; ohi.w = v > 0.f ? v : 0.01f * v;
        *(float4*)(g_H + (size_t)grl * DHID + col0 + tx * 4) = olo;
        *(float4*)(g_H + (size_t)(grl + 1) * DHID + col0 + tx * 4) = ohi;
    }
}

// GEMM2 (split-K=4): part[z] = H[:, z*256:(z+1)*256] @ W2[z*256:(z+1)*256, :]
__global__ __launch_bounds__(256) void k_gemm2(const float* __restrict__ W2)
{
    __shared__ float As[GBK][GBM];
    __shared__ float Bs2[GBK][2 * GBN];
    const int bn = blockIdx.x;            // 0..3
    const int bm = blockIdx.y;            // 0..11
    const int kz = blockIdx.z;            // 0..3
    const int tid = threadIdx.x;
    const int tx = tid & 15, ty = tid >> 4;
    const int row0 = bm * GBM, col0 = bn * GBN;
    const int kbeg = kz * 256;

    const int am  = tid >> 2;
    const int akq = (tid & 3) * 4;
    const int bk_ = tid >> 4;
    const int bnq = (tid & 15) * 4;

    uint64_t acc[4][4];
#pragma unroll
    for (int r = 0; r < 4; r++)
#pragma unroll
        for (int c = 0; c < 4; c++) acc[r][c] = 0ull;

    for (int k0 = kbeg; k0 < kbeg + 256; k0 += GBK) {
#pragma unroll
        for (int rr = 0; rr < 2; rr++) {
            int m = am + rr * 64;
            int gr = row0 + m;
            float4 av = *(const float4*)(g_H + (size_t)gr * DHID + k0 + akq);
            As[akq + 0][m] = av.x; As[akq + 1][m] = av.y;
            As[akq + 2][m] = av.z; As[akq + 3][m] = av.w;
        }
        {
            float4 bv = *(const float4*)(W2 + (size_t)(k0 + bk_) * UNITS + col0 + bnq);
            float2* bp = (float2*)&Bs2[bk_][2 * bnq];
            bp[0] = make_float2(bv.x, bv.x);
            bp[1] = make_float2(bv.y, bv.y);
            bp[2] = make_float2(bv.z, bv.z);
            bp[3] = make_float2(bv.w, bv.w);
        }
        __syncthreads();
#pragma unroll
        for (int kk = 0; kk < GBK; kk++) {
            ulonglong2 a01 = *(const ulonglong2*)&As[kk][ty * 8];
            ulonglong2 a23 = *(const ulonglong2*)&As[kk][ty * 8 + 4];
            ulonglong2 b01 = *(const ulonglong2*)&Bs2[kk][tx * 8];
            ulonglong2 b23 = *(const ulonglong2*)&Bs2[kk][tx * 8 + 4];
            FMA2(acc[0][0], a01.x, b01.x); FMA2(acc[0][1], a01.x, b01.y);
            FMA2(acc[0][2], a01.x, b23.x); FMA2(acc[0][3], a01.x, b23.y);
            FMA2(acc[1][0], a01.y, b01.x); FMA2(acc[1][1], a01.y, b01.y);
            FMA2(acc[1][2], a01.y, b23.x); FMA2(acc[1][3], a01.y, b23.y);
            FMA2(acc[2][0], a23.x, b01.x); FMA2(acc[2][1], a23.x, b01.y);
            FMA2(acc[2][2], a23.x, b23.x); FMA2(acc[2][3], a23.x, b23.y);
            FMA2(acc[3][0], a23.y, b01.x); FMA2(acc[3][1], a23.y, b01.y);
            FMA2(acc[3][2], a23.y, b23.x); FMA2(acc[3][3], a23.y, b23.y);
        }
        __syncthreads();
    }
    float* outp = g_part + (size_t)kz * BATCH2 * UNITS;
    const int r0 = ty * 8;
#pragma unroll
    for (int rp = 0; rp < 4; rp++) {
        float lo[4], hi[4];
#pragma unroll
        for (int c = 0; c < 4; c++) unpack2(acc[rp][c], lo[c], hi[c]);
        int grl = row0 + r0 + rp * 2;
        *(float4*)(outp + (size_t)grl * UNITS + col0 + tx * 4) =
            make_float4(lo[0], lo[1], lo[2], lo[3]);
        *(float4*)(outp + (size_t)(grl + 1) * UNITS + col0 + tx * 4) =
            make_float4(hi[0], hi[1], hi[2], hi[3]);
    }
}

// ---------------- reduce split-K, add b2, build exp tables ----------------
__global__ void k_reduce_exp(const float* __restrict__ b2,
                             const float* __restrict__ temp)
{
    int idx = blockIdx.x * blockDim.x + threadIdx.x;  // 0 .. 1536*256-1
    if (idx >= BATCH2 * UNITS) return;
    int row = idx >> 8;
    int u = idx & 255;
    const int S = BATCH2 * UNITS;
    float v = g_part[idx] + g_part[idx + S] + g_part[idx + 2 * S]
            + g_part[idx + 3 * S] + b2[u];
    float e = expf(v * temp[u]);
    float ie = 1.0f / e;
    if (row < BATCH) {
        g_Ek [row * UNITS + u] = e;
        g_iEk[row * UNITS + u] = ie;
    } else {
        g_Eq [(row - BATCH) * UNITS + u] = e;
        g_iEq[(row - BATCH) * UNITS + u] = ie;
    }
}

// ---------------- fused softmax + write (the 604MB kernel) ----------------
// exp(-|k-q|t) = min(Ek*invEq, Eq*invEk).  Thread owns (j2, u), keeps
// Ek/invEk for its 96 j1 values in registers. Two register passes per i:
// group sum (diagonal excluded), then normalized store.
#define NBI 37
__global__ __launch_bounds__(256, 1) void k_softmax_write(float* __restrict__ w)
{
    const int uc = blockIdx.x;                 // 0..7
    const int ib = blockIdx.y;                 // 0..NBI-1
    const int lane = threadIdx.x & 31;
    const int j2 = threadIdx.x >> 5;           // 0..7
    const int u = uc * 32 + lane;

    float ek[J1N], iek[J1N];
    const float* Ekp  = g_Ek  + j2 * UNITS + u;
    const float* iEkp = g_iEk + j2 * UNITS + u;
#pragma unroll
    for (int j1 = 0; j1 < J1N; j1++) {
        ek[j1]  = Ekp [j1 * (GROUPS * UNITS)];
        iek[j1] = iEkp[j1 * (GROUPS * UNITS)];
    }

    const int i0 = (ib * BATCH) / NBI;
    const int i1 = ((ib + 1) * BATCH) / NBI;
    for (int i = i0; i < i1; i++) {
        float eq  = g_Eq [i * UNITS + u];
        float ieq = g_iEq[i * UNITS + u];
        float s = 0.f;
#pragma unroll
        for (int j1 = 0; j1 < J1N; j1++)
            s += fminf(ek[j1] * ieq, iek[j1] * eq);
        bool diag = ((i & 7) == j2);
        int jd = i >> 3;
        if (diag) s -= fminf(ek[jd] * ieq, iek[jd] * eq);
        float r = 1.0f / (8.0f * s);
        float f1 = ieq * r, f2 = eq * r;
        float* base = w + ((size_t)i * BATCH + j2) * UNITS + u;
#pragma unroll
        for (int j1 = 0; j1 < J1N; j1++)
            base[(size_t)j1 * (GROUPS * UNITS)] =
                fminf(ek[j1] * f1, iek[j1] * f2);
        if (diag) base[(size_t)jd * (GROUPS * UNITS)] = 0.0f;
    }
}

// ---------------- optional mask tail of the tuple output -----------------
__global__ void k_mask_tail(float* __restrict__ out, const void* __restrict__ mask,
                            long long extra)
{
    long long idx = (long long)blockIdx.x * blockDim.x + threadIdx.x;
    if (idx >= extra) return;
    float v = 0.0f;
    if (idx < BATCH * UNITS)
        v = mask_at(mask, g_mask_mode, (int)idx) ? 1.0f : 0.0f;
    out[idx] = v;
}

// ---------------- launch ----------------
extern "C" void kernel_launch(void* const* d_in, const int* in_sizes, int n_in,
                              void* d_out, int out_size)
{
    const float* x    = (const float*)d_in[0];
    const void*  mask = d_in[1];
    const float* W1   = (const float*)d_in[2];
    const float* b1   = (const float*)d_in[3];
    const float* W2   = (const float*)d_in[4];
    const float* b2   = (const float*)d_in[5];
    const float* temp = (const float*)d_in[6];
    float* out = (float*)d_out;

    // H = leaky(X2 @ W1 + b1)   (mask-mode detection inlined)
    k_gemm1<<<dim3(DHID / GBN, BATCH2 / GBM), 256>>>(x, mask, W1, b1);

    // partials = H @ W2 (split-K)
    k_gemm2<<<dim3(UNITS / GBN, BATCH2 / GBM, 4), 256>>>(W2);

    // key/query + exp tables
    k_reduce_exp<<<(BATCH2 * UNITS + 255) / 256, 256>>>(b2, temp);

    // big fused softmax + write
    k_softmax_write<<<dim3(UNITS / 32, NBI), 256>>>(out);

    // if output is the whole tuple (w, mask), fill the mask tail
    long long extra = (long long)out_size - W_ELEMS;
    if (extra > 0) {
        k_detect_mask<<<1, 256>>>((const unsigned char*)mask);
        int nb = (int)((extra + 255) / 256);
        k_mask_tail<<<nb, 256>>>(out + W_ELEMS, mask, extra);
    }
}

// round 6
// speedup vs baseline: 1.2638x; 1.2638x over previous
#include <cuda_runtime.h>
#include <cuda_bf16.h>
#include <cstdint>
#include <cstddef>
#include <math.h>

// Problem constants
#define BATCH 768
#define UNITS 256
#define DHID  1024
#define GROUPS 8
#define J1N   96              // BATCH / GROUPS
#define BATCH2 1536           // 2 * BATCH (key rows then query rows)
#define W_ELEMS 150994944ll   // 768*768*256

// ---------------- device scratch (no allocations allowed) ----------------
__device__ float g_H[BATCH2 * DHID];          // hidden activations (leaky), 6.3MB
__device__ float g_part[4 * BATCH2 * UNITS];  // split-K partials for GEMM2
__device__ float g_Ek [BATCH * UNITS];        // exp(key*t)
__device__ float g_iEk[BATCH * UNITS];        // 1/exp(key*t)
__device__ float g_Eq [BATCH * UNITS];        // exp(query*t)
__device__ float g_iEq[BATCH * UNITS];        // 1/exp(query*t)
__device__ int   g_mask_mode;                 // 0=f32, 1=bf16, 2=i32, 3=u8

__device__ __forceinline__ bool mask_at(const void* m, int mode, int idx) {
    switch (mode) {
        case 0:  return ((const float*)m)[idx] != 0.0f;
        case 1:  return ((const unsigned short*)m)[idx] != 0;
        case 2:  return ((const int*)m)[idx] != 0;
        default: return ((const unsigned char*)m)[idx] != 0;
    }
}

// ---------------- standalone mask dtype detection (tail path only) -------
__global__ void k_detect_mask(const unsigned char* __restrict__ m) {
    __shared__ int ok[4];
    if (threadIdx.x < 4) ok[threadIdx.x] = 1;
    __syncthreads();
    const unsigned int* w = (const unsigned int*)m;
    for (int idx = threadIdx.x; idx < 256; idx += blockDim.x) {
        unsigned int v = w[idx];
        if (!(v == 0u || v == 0x3F800000u)) atomicAnd(&ok[0], 0);
        unsigned int h0 = v & 0xFFFFu, h1 = v >> 16;
        if (!((h0 == 0u || h0 == 0x3F80u) && (h1 == 0u || h1 == 0x3F80u)))
            atomicAnd(&ok[1], 0);
        if (v > 1u) atomicAnd(&ok[2], 0);
        if ((v & 0xFEFEFEFEu) != 0u) atomicAnd(&ok[3], 0);
    }
    __syncthreads();
    if (threadIdx.x == 0)
        g_mask_mode = ok[0] ? 0 : (ok[1] ? 1 : (ok[2] ? 2 : 3));
}

// ---------------- GEMM1: H[1536,1024] = leaky(X2[1536,256] @ W1 + b1) ----
// (R2 version — measured good. X2 rows 0..767 = x, rows 768..1535 = masked x.)
#define BM 64
#define BN 64
#define BK 16

__global__ __launch_bounds__(256) void k_gemm1(
    const float* __restrict__ x, const void* __restrict__ mask,
    const float* __restrict__ W1, const float* __restrict__ b1)
{
    __shared__ float As[BK][BM];
    __shared__ float Bs[BK][BN];
    const int tid = threadIdx.x;

    // inline mask dtype detection (uniform result, cheap barriers)
    {
        unsigned int v = ((const unsigned int*)mask)[tid];
        unsigned int h0 = v & 0xFFFFu, h1 = v >> 16;
        int m_f32 = __syncthreads_and((v == 0u) || (v == 0x3F800000u));
        int m_bf  = __syncthreads_and((h0 == 0u || h0 == 0x3F80u) &&
                                      (h1 == 0u || h1 == 0x3F80u));
        int m_i32 = __syncthreads_and(v <= 1u);
        g_mask_mode = m_f32 ? 0 : (m_bf ? 1 : (m_i32 ? 2 : 3));
    }
    const int mmode = g_mask_mode;

    const int bn = blockIdx.x;            // 0..15
    const int bm = blockIdx.y;            // 0..23
    const int tx = tid & 15, ty = tid >> 4;
    const int row0 = bm * BM, col0 = bn * BN;

    const int am  = tid >> 2;             // 0..63 (row in tile)
    const int akq = (tid & 3) * 4;        // 0,4,8,12 (k quad)
    const int bk_ = tid >> 4;             // 0..15 (k in tile)
    const int bnq = (tid & 15) * 4;       // n quad

    float acc[4][4];
#pragma unroll
    for (int r = 0; r < 4; r++)
#pragma unroll
        for (int c = 0; c < 4; c++) acc[r][c] = 0.f;

    for (int k0 = 0; k0 < UNITS; k0 += BK) {
        int gr = row0 + am;
        float4 av;
        if (gr < BATCH) {
            av = *(const float4*)(x + gr * UNITS + k0 + akq);
        } else {
            int r = gr - BATCH;
            int base = r * UNITS + k0 + akq;
            av = *(const float4*)(x + base);
            if (mask_at(mask, mmode, base + 0)) av.x = 0.f;
            if (mask_at(mask, mmode, base + 1)) av.y = 0.f;
            if (mask_at(mask, mmode, base + 2)) av.z = 0.f;
            if (mask_at(mask, mmode, base + 3)) av.w = 0.f;
        }
        As[akq + 0][am] = av.x; As[akq + 1][am] = av.y;
        As[akq + 2][am] = av.z; As[akq + 3][am] = av.w;
        *(float4*)&Bs[bk_][bnq] =
            *(const float4*)(W1 + (size_t)(k0 + bk_) * DHID + col0 + bnq);
        __syncthreads();
#pragma unroll
        for (int kk = 0; kk < BK; kk++) {
            float4 a4 = *(const float4*)&As[kk][ty * 4];
            float4 b4 = *(const float4*)&Bs[kk][tx * 4];
            float a[4] = {a4.x, a4.y, a4.z, a4.w};
            float b[4] = {b4.x, b4.y, b4.z, b4.w};
#pragma unroll
            for (int r = 0; r < 4; r++)
#pragma unroll
                for (int c = 0; c < 4; c++) acc[r][c] += a[r] * b[c];
        }
        __syncthreads();
    }
    float4 bb = *(const float4*)(b1 + col0 + tx * 4);
    float bias[4] = {bb.x, bb.y, bb.z, bb.w};
#pragma unroll
    for (int r = 0; r < 4; r++) {
        int gm = row0 + ty * 4 + r;
        float4 o;
        float v0 = acc[r][0] + bias[0]; o.x = v0 > 0.f ? v0 : 0.01f * v0;
        float v1 = acc[r][1] + bias[1]; o.y = v1 > 0.f ? v1 : 0.01f * v1;
        float v2 = acc[r][2] + bias[2]; o.z = v2 > 0.f ? v2 : 0.01f * v2;
        float v3 = acc[r][3] + bias[3]; o.w = v3 > 0.f ? v3 : 0.01f * v3;
        *(float4*)(g_H + (size_t)gm * DHID + col0 + tx * 4) = o;
    }
}

// ---------------- GEMM2 (split-K=4): part[z] = H[:,z*256:(z+1)*256] @ W2 --
__global__ __launch_bounds__(256) void k_gemm2(const float* __restrict__ W2)
{
    __shared__ float As[BK][BM];
    __shared__ float Bs[BK][BN];
    const int bn = blockIdx.x;            // 0..3
    const int bm = blockIdx.y;            // 0..23
    const int kz = blockIdx.z;            // 0..3
    const int tid = threadIdx.x;
    const int tx = tid & 15, ty = tid >> 4;
    const int row0 = bm * BM, col0 = bn * BN;
    const int kbeg = kz * 256;

    const int am  = tid >> 2;
    const int akq = (tid & 3) * 4;
    const int bk_ = tid >> 4;
    const int bnq = (tid & 15) * 4;

    float acc[4][4];
#pragma unroll
    for (int r = 0; r < 4; r++)
#pragma unroll
        for (int c = 0; c < 4; c++) acc[r][c] = 0.f;

    for (int k0 = kbeg; k0 < kbeg + 256; k0 += BK) {
        int gr = row0 + am;
        float4 av = *(const float4*)(g_H + (size_t)gr * DHID + k0 + akq);
        As[akq + 0][am] = av.x; As[akq + 1][am] = av.y;
        As[akq + 2][am] = av.z; As[akq + 3][am] = av.w;
        *(float4*)&Bs[bk_][bnq] =
            *(const float4*)(W2 + (size_t)(k0 + bk_) * UNITS + col0 + bnq);
        __syncthreads();
#pragma unroll
        for (int kk = 0; kk < BK; kk++) {
            float4 a4 = *(const float4*)&As[kk][ty * 4];
            float4 b4 = *(const float4*)&Bs[kk][tx * 4];
            float a[4] = {a4.x, a4.y, a4.z, a4.w};
            float b[4] = {b4.x, b4.y, b4.z, b4.w};
#pragma unroll
            for (int r = 0; r < 4; r++)
#pragma unroll
                for (int c = 0; c < 4; c++) acc[r][c] += a[r] * b[c];
        }
        __syncthreads();
    }
    float* outp = g_part + (size_t)kz * BATCH2 * UNITS;
#pragma unroll
    for (int r = 0; r < 4; r++) {
        int gm = row0 + ty * 4 + r;
        float4 o = make_float4(acc[r][0], acc[r][1], acc[r][2], acc[r][3]);
        *(float4*)(outp + (size_t)gm * UNITS + col0 + tx * 4) = o;
    }
}

// ---------------- reduce split-K, add b2, build exp tables ----------------
__global__ void k_reduce_exp(const float* __restrict__ b2,
                             const float* __restrict__ temp)
{
    int idx = blockIdx.x * blockDim.x + threadIdx.x;  // 0 .. 1536*256-1
    if (idx >= BATCH2 * UNITS) return;
    int row = idx >> 8;
    int u = idx & 255;
    const int S = BATCH2 * UNITS;
    float v = g_part[idx] + g_part[idx + S] + g_part[idx + 2 * S]
            + g_part[idx + 3 * S] + b2[u];
    float e = expf(v * temp[u]);
    float ie = 1.0f / e;
    if (row < BATCH) {
        g_Ek [row * UNITS + u] = e;
        g_iEk[row * UNITS + u] = ie;
    } else {
        g_Eq [(row - BATCH) * UNITS + u] = e;
        g_iEq[(row - BATCH) * UNITS + u] = ie;
    }
}

// ---------------- fused softmax + write (the 604MB kernel) ----------------
// exp(-|k-q|t) = min(Ek*invEq, Eq*invEk).  Thread owns (j2, u) and HALF the
// j1 range (48 entries of Ek/invEk in registers -> ~120 regs -> 2 blocks/SM).
// The two halves combine their partial group-sums through one smem exchange.
// Block covers: 32 u (lane) x 4 j2 (jj) x 2 j1-halves (h) = 256 threads.
#define NBI2 18
__global__ __launch_bounds__(256, 2) void k_softmax_write(float* __restrict__ w)
{
    __shared__ float sbuf[256];
    const int uc  = blockIdx.x & 7;        // u chunk 0..7
    const int j2h = (blockIdx.x >> 3) & 1; // j2 half 0..1
    const int ib  = blockIdx.y;            // 0..NBI2-1
    const int tid = threadIdx.x;
    const int lane = tid & 31;
    const int jj  = (tid >> 5) & 3;        // 0..3
    const int h   = tid >> 7;              // 0..1 (j1 half)
    const int j2  = j2h * 4 + jj;
    const int u   = uc * 32 + lane;
    const int j1base = h * 48;

    float ek[48], iek[48];
    const float* Ekp  = g_Ek  + ((j1base * GROUPS + j2) * UNITS) + u;
    const float* iEkp = g_iEk + ((j1base * GROUPS + j2) * UNITS) + u;
#pragma unroll
    for (int t = 0; t < 48; t++) {
        ek[t]  = Ekp [t * (GROUPS * UNITS)];
        iek[t] = iEkp[t * (GROUPS * UNITS)];
    }

    const int i0 = (ib * BATCH) / NBI2;
    const int i1 = ((ib + 1) * BATCH) / NBI2;
    for (int i = i0; i < i1; i++) {
        float eq  = g_Eq [i * UNITS + u];
        float ieq = g_iEq[i * UNITS + u];
        float s = 0.f;
#pragma unroll
        for (int t = 0; t < 48; t++)
            s += fminf(ek[t] * ieq, iek[t] * eq);
        // diagonal exclusion: j == i  ->  j1 = i>>3 (maybe in this half), j2 = i&7
        int jd = (i >> 3) - j1base;
        bool diag = ((i & 7) == j2) && (jd >= 0) && (jd < 48);
        if (diag) s -= fminf(ek[jd] * ieq, iek[jd] * eq);
        // combine the two j1-halves of this (j2, u) group
        sbuf[tid] = s;
        __syncthreads();
        float stot = s + sbuf[tid ^ 128];
        __syncthreads();   // protect sbuf for next iteration
        float r = 1.0f / (8.0f * stot);
        float f1 = ieq * r, f2 = eq * r;
        float* base = w + ((size_t)i * BATCH + j1base * GROUPS + j2) * UNITS + u;
#pragma unroll
        for (int t = 0; t < 48; t++)
            base[(size_t)t * (GROUPS * UNITS)] =
                fminf(ek[t] * f1, iek[t] * f2);
        if (diag) base[(size_t)jd * (GROUPS * UNITS)] = 0.0f;
    }
}

// ---------------- optional mask tail of the tuple output -----------------
__global__ void k_mask_tail(float* __restrict__ out, const void* __restrict__ mask,
                            long long extra)
{
    long long idx = (long long)blockIdx.x * blockDim.x + threadIdx.x;
    if (idx >= extra) return;
    float v = 0.0f;
    if (idx < BATCH * UNITS)
        v = mask_at(mask, g_mask_mode, (int)idx) ? 1.0f : 0.0f;
    out[idx] = v;
}

// ---------------- launch ----------------
extern "C" void kernel_launch(void* const* d_in, const int* in_sizes, int n_in,
                              void* d_out, int out_size)
{
    const float* x    = (const float*)d_in[0];
    const void*  mask = d_in[1];
    const float* W1   = (const float*)d_in[2];
    const float* b1   = (const float*)d_in[3];
    const float* W2   = (const float*)d_in[4];
    const float* b2   = (const float*)d_in[5];
    const float* temp = (const float*)d_in[6];
    float* out = (float*)d_out;

    // H = leaky(X2 @ W1 + b1)   (mask-mode detection inlined)
    k_gemm1<<<dim3(DHID / BN, BATCH2 / BM), 256>>>(x, mask, W1, b1);

    // partials = H @ W2 (split-K)
    k_gemm2<<<dim3(UNITS / BN, BATCH2 / BM, 4), 256>>>(W2);

    // key/query + exp tables
    k_reduce_exp<<<(BATCH2 * UNITS + 255) / 256, 256>>>(b2, temp);

    // big fused softmax + write: grid = 8 u-chunks x 2 j2-halves x NBI2 i-blocks
    k_softmax_write<<<dim3(16, NBI2), 256>>>(out);

    // if output is the whole tuple (w, mask), fill the mask tail
    long long extra = (long long)out_size - W_ELEMS;
    if (extra > 0) {
        k_detect_mask<<<1, 256>>>((const unsigned char*)mask);
        int nb = (int)((extra + 255) / 256);
        k_mask_tail<<<nb, 256>>>(out + W_ELEMS, mask, extra);
    }
}

// round 12
// speedup vs baseline: 1.3855x; 1.0963x over previous
#include <cuda_runtime.h>
#include <cuda_bf16.h>
#include <cstdint>
#include <cstddef>
#include <math.h>

// Problem constants
#define BATCH 768
#define UNITS 256
#define DHID  1024
#define GROUPS 8
#define J1N   96              // BATCH / GROUPS
#define BATCH2 1536           // 2 * BATCH (key rows then query rows)
#define W_ELEMS 150994944ll   // 768*768*256

// ---------------- device scratch (no allocations allowed) ----------------
__device__ float g_H[BATCH2 * DHID];          // hidden activations (leaky), 6.3MB
__device__ float g_part[4 * BATCH2 * UNITS];  // split-K partials for GEMM2
__device__ float g_Ek [BATCH * UNITS];        // exp(key*t)
__device__ float g_iEk[BATCH * UNITS];        // 1/exp(key*t)
__device__ float g_Eq [BATCH * UNITS];        // exp(query*t)
__device__ float g_iEq[BATCH * UNITS];        // 1/exp(query*t)
__device__ int   g_mask_mode;                 // 0=f32, 1=bf16, 2=i32, 3=u8

__device__ __forceinline__ bool mask_at(const void* m, int mode, int idx) {
    switch (mode) {
        case 0:  return ((const float*)m)[idx] != 0.0f;
        case 1:  return ((const unsigned short*)m)[idx] != 0;
        case 2:  return ((const int*)m)[idx] != 0;
        default: return ((const unsigned char*)m)[idx] != 0;
    }
}

// ---------------- standalone mask dtype detection (tail path only) -------
__global__ void k_detect_mask(const unsigned char* __restrict__ m) {
    __shared__ int ok[4];
    if (threadIdx.x < 4) ok[threadIdx.x] = 1;
    __syncthreads();
    const unsigned int* w = (const unsigned int*)m;
    for (int idx = threadIdx.x; idx < 256; idx += blockDim.x) {
        unsigned int v = w[idx];
        if (!(v == 0u || v == 0x3F800000u)) atomicAnd(&ok[0], 0);
        unsigned int h0 = v & 0xFFFFu, h1 = v >> 16;
        if (!((h0 == 0u || h0 == 0x3F80u) && (h1 == 0u || h1 == 0x3F80u)))
            atomicAnd(&ok[1], 0);
        if (v > 1u) atomicAnd(&ok[2], 0);
        if ((v & 0xFEFEFEFEu) != 0u) atomicAnd(&ok[3], 0);
    }
    __syncthreads();
    if (threadIdx.x == 0)
        g_mask_mode = ok[0] ? 0 : (ok[1] ? 1 : (ok[2] ? 2 : 3));
}

// ---------------- GEMM1: H[1536,1024] = leaky(X2[1536,256] @ W1 + b1) ----
// (R2 version — measured good. X2 rows 0..767 = x, rows 768..1535 = masked x.)
#define BM 64
#define BN 64
#define BK 16

__global__ __launch_bounds__(256) void k_gemm1(
    const float* __restrict__ x, const void* __restrict__ mask,
    const float* __restrict__ W1, const float* __restrict__ b1)
{
    __shared__ float As[BK][BM];
    __shared__ float Bs[BK][BN];
    const int tid = threadIdx.x;

    // inline mask dtype detection (uniform result, cheap barriers)
    {
        unsigned int v = ((const unsigned int*)mask)[tid];
        unsigned int h0 = v & 0xFFFFu, h1 = v >> 16;
        int m_f32 = __syncthreads_and((v == 0u) || (v == 0x3F800000u));
        int m_bf  = __syncthreads_and((h0 == 0u || h0 == 0x3F80u) &&
                                      (h1 == 0u || h1 == 0x3F80u));
        int m_i32 = __syncthreads_and(v <= 1u);
        g_mask_mode = m_f32 ? 0 : (m_bf ? 1 : (m_i32 ? 2 : 3));
    }
    const int mmode = g_mask_mode;

    const int bn = blockIdx.x;            // 0..15
    const int bm = blockIdx.y;            // 0..23
    const int tx = tid & 15, ty = tid >> 4;
    const int row0 = bm * BM, col0 = bn * BN;

    const int am  = tid >> 2;             // 0..63 (row in tile)
    const int akq = (tid & 3) * 4;        // 0,4,8,12 (k quad)
    const int bk_ = tid >> 4;             // 0..15 (k in tile)
    const int bnq = (tid & 15) * 4;       // n quad

    float acc[4][4];
#pragma unroll
    for (int r = 0; r < 4; r++)
#pragma unroll
        for (int c = 0; c < 4; c++) acc[r][c] = 0.f;

    for (int k0 = 0; k0 < UNITS; k0 += BK) {
        int gr = row0 + am;
        float4 av;
        if (gr < BATCH) {
            av = *(const float4*)(x + gr * UNITS + k0 + akq);
        } else {
            int r = gr - BATCH;
            int base = r * UNITS + k0 + akq;
            av = *(const float4*)(x + base);
            if (mask_at(mask, mmode, base + 0)) av.x = 0.f;
            if (mask_at(mask, mmode, base + 1)) av.y = 0.f;
            if (mask_at(mask, mmode, base + 2)) av.z = 0.f;
            if (mask_at(mask, mmode, base + 3)) av.w = 0.f;
        }
        As[akq + 0][am] = av.x; As[akq + 1][am] = av.y;
        As[akq + 2][am] = av.z; As[akq + 3][am] = av.w;
        *(float4*)&Bs[bk_][bnq] =
            *(const float4*)(W1 + (size_t)(k0 + bk_) * DHID + col0 + bnq);
        __syncthreads();
#pragma unroll
        for (int kk = 0; kk < BK; kk++) {
            float4 a4 = *(const float4*)&As[kk][ty * 4];
            float4 b4 = *(const float4*)&Bs[kk][tx * 4];
            float a[4] = {a4.x, a4.y, a4.z, a4.w};
            float b[4] = {b4.x, b4.y, b4.z, b4.w};
#pragma unroll
            for (int r = 0; r < 4; r++)
#pragma unroll
                for (int c = 0; c < 4; c++) acc[r][c] += a[r] * b[c];
        }
        __syncthreads();
    }
    float4 bb = *(const float4*)(b1 + col0 + tx * 4);
    float bias[4] = {bb.x, bb.y, bb.z, bb.w};
#pragma unroll
    for (int r = 0; r < 4; r++) {
        int gm = row0 + ty * 4 + r;
        float4 o;
        float v0 = acc[r][0] + bias[0]; o.x = v0 > 0.f ? v0 : 0.01f * v0;
        float v1 = acc[r][1] + bias[1]; o.y = v1 > 0.f ? v1 : 0.01f * v1;
        float v2 = acc[r][2] + bias[2]; o.z = v2 > 0.f ? v2 : 0.01f * v2;
        float v3 = acc[r][3] + bias[3]; o.w = v3 > 0.f ? v3 : 0.01f * v3;
        *(float4*)(g_H + (size_t)gm * DHID + col0 + tx * 4) = o;
    }
}

// ---------------- GEMM2 (split-K=4): part[z] = H[:,z*256:(z+1)*256] @ W2 --
__global__ __launch_bounds__(256) void k_gemm2(const float* __restrict__ W2)
{
    __shared__ float As[BK][BM];
    __shared__ float Bs[BK][BN];
    const int bn = blockIdx.x;            // 0..3
    const int bm = blockIdx.y;            // 0..23
    const int kz = blockIdx.z;            // 0..3
    const int tid = threadIdx.x;
    const int tx = tid & 15, ty = tid >> 4;
    const int row0 = bm * BM, col0 = bn * BN;
    const int kbeg = kz * 256;

    const int am  = tid >> 2;
    const int akq = (tid & 3) * 4;
    const int bk_ = tid >> 4;
    const int bnq = (tid & 15) * 4;

    float acc[4][4];
#pragma unroll
    for (int r = 0; r < 4; r++)
#pragma unroll
        for (int c = 0; c < 4; c++) acc[r][c] = 0.f;

    for (int k0 = kbeg; k0 < kbeg + 256; k0 += BK) {
        int gr = row0 + am;
        float4 av = *(const float4*)(g_H + (size_t)gr * DHID + k0 + akq);
        As[akq + 0][am] = av.x; As[akq + 1][am] = av.y;
        As[akq + 2][am] = av.z; As[akq + 3][am] = av.w;
        *(float4*)&Bs[bk_][bnq] =
            *(const float4*)(W2 + (size_t)(k0 + bk_) * UNITS + col0 + bnq);
        __syncthreads();
#pragma unroll
        for (int kk = 0; kk < BK; kk++) {
            float4 a4 = *(const float4*)&As[kk][ty * 4];
            float4 b4 = *(const float4*)&Bs[kk][tx * 4];
            float a[4] = {a4.x, a4.y, a4.z, a4.w};
            float b[4] = {b4.x, b4.y, b4.z, b4.w};
#pragma unroll
            for (int r = 0; r < 4; r++)
#pragma unroll
                for (int c = 0; c < 4; c++) acc[r][c] += a[r] * b[c];
        }
        __syncthreads();
    }
    float* outp = g_part + (size_t)kz * BATCH2 * UNITS;
#pragma unroll
    for (int r = 0; r < 4; r++) {
        int gm = row0 + ty * 4 + r;
        float4 o = make_float4(acc[r][0], acc[r][1], acc[r][2], acc[r][3]);
        *(float4*)(outp + (size_t)gm * UNITS + col0 + tx * 4) = o;
    }
}

// ---------------- reduce split-K, add b2, build exp tables (float4) ------
__global__ void k_reduce_exp(const float* __restrict__ b2,
                             const float* __restrict__ temp)
{
    int q = blockIdx.x * blockDim.x + threadIdx.x;   // quad index
    if (q >= BATCH2 * UNITS / 4) return;
    int idx = q * 4;
    int row = idx >> 8;
    int uq = idx & 255;
    const int S = BATCH2 * UNITS;
    float4 p0 = *(const float4*)(g_part + idx);
    float4 p1 = *(const float4*)(g_part + idx + S);
    float4 p2 = *(const float4*)(g_part + idx + 2 * S);
    float4 p3 = *(const float4*)(g_part + idx + 3 * S);
    float4 bb = *(const float4*)(b2 + uq);
    float4 tt = *(const float4*)(temp + uq);
    float4 e, ie;
    e.x = expf((p0.x + p1.x + p2.x + p3.x + bb.x) * tt.x); ie.x = 1.0f / e.x;
    e.y = expf((p0.y + p1.y + p2.y + p3.y + bb.y) * tt.y); ie.y = 1.0f / e.y;
    e.z = expf((p0.z + p1.z + p2.z + p3.z + bb.z) * tt.z); ie.z = 1.0f / e.z;
    e.w = expf((p0.w + p1.w + p2.w + p3.w + bb.w) * tt.w); ie.w = 1.0f / e.w;
    if (row < BATCH) {
        *(float4*)(g_Ek  + idx) = e;
        *(float4*)(g_iEk + idx) = ie;
    } else {
        int o = idx - BATCH * UNITS;
        *(float4*)(g_Eq  + o) = e;
        *(float4*)(g_iEq + o) = ie;
    }
}

// ---------------- fused softmax + write (the 604MB kernel) ----------------
// exp(-|k-q|t) = min(Ek*invEq, Eq*invEk).  Block owns ONE j2 and ALL 256 u
// (warp = u-chunk), so at each j1 step the block writes one CONTIGUOUS 1KB
// line of w[i][j1*8+j2][0..255].  Thread keeps Ek/invEk for its (j2,u) over
// all 96 j1 in registers.  Streaming stores (st.global.cs): output is never
// re-read, keep it out of L2's way.
#define NBI 37
__global__ __launch_bounds__(256, 1) void k_softmax_write(float* __restrict__ w)
{
    const int j2 = blockIdx.x;                 // 0..7
    const int ib = blockIdx.y;                 // 0..NBI-1
    const int lane = threadIdx.x & 31;
    const int uc = threadIdx.x >> 5;           // 0..7 (u chunk)
    const int u = uc * 32 + lane;

    float ek[J1N], iek[J1N];
    const float* Ekp  = g_Ek  + j2 * UNITS + u;
    const float* iEkp = g_iEk + j2 * UNITS + u;
#pragma unroll
    for (int j1 = 0; j1 < J1N; j1++) {
        ek[j1]  = Ekp [j1 * (GROUPS * UNITS)];
        iek[j1] = iEkp[j1 * (GROUPS * UNITS)];
    }

    const int i0 = (ib * BATCH) / NBI;
    const int i1 = ((ib + 1) * BATCH) / NBI;
    for (int i = i0; i < i1; i++) {
        float eq  = g_Eq [i * UNITS + u];
        float ieq = g_iEq[i * UNITS + u];
        float s = 0.f;
#pragma unroll
        for (int j1 = 0; j1 < J1N; j1++)
            s += fminf(ek[j1] * ieq, iek[j1] * eq);
        const bool diag = ((i & 7) == j2);     // uniform across block
        const int jd = i >> 3;
        if (diag) s -= fminf(ek[jd] * ieq, iek[jd] * eq);
        float r = 1.0f / (8.0f * s);
        float f1 = ieq * r, f2 = eq * r;
        float* base = w + ((size_t)i * BATCH + j2) * UNITS + u;
#pragma unroll
        for (int j1 = 0; j1 < J1N; j1++)
            __stcs(base + (size_t)j1 * (GROUPS * UNITS),
                   fminf(ek[j1] * f1, iek[j1] * f2));
        if (diag) __stcs(base + (size_t)jd * (GROUPS * UNITS), 0.0f);
    }
}

// ---------------- optional mask tail of the tuple output -----------------
__global__ void k_mask_tail(float* __restrict__ out, const void* __restrict__ mask,
                            long long extra)
{
    long long idx = (long long)blockIdx.x * blockDim.x + threadIdx.x;
    if (idx >= extra) return;
    float v = 0.0f;
    if (idx < BATCH * UNITS)
        v = mask_at(mask, g_mask_mode, (int)idx) ? 1.0f : 0.0f;
    out[idx] = v;
}

// ---------------- launch ----------------
extern "C" void kernel_launch(void* const* d_in, const int* in_sizes, int n_in,
                              void* d_out, int out_size)
{
    const float* x    = (const float*)d_in[0];
    const void*  mask = d_in[1];
    const float* W1   = (const float*)d_in[2];
    const float* b1   = (const float*)d_in[3];
    const float* W2   = (const float*)d_in[4];
    const float* b2   = (const float*)d_in[5];
    const float* temp = (const float*)d_in[6];
    float* out = (float*)d_out;

    // H = leaky(X2 @ W1 + b1)   (mask-mode detection inlined)
    k_gemm1<<<dim3(DHID / BN, BATCH2 / BM), 256>>>(x, mask, W1, b1);

    // partials = H @ W2 (split-K)
    k_gemm2<<<dim3(UNITS / BN, BATCH2 / BM, 4), 256>>>(W2);

    // key/query + exp tables
    k_reduce_exp<<<(BATCH2 * UNITS / 4 + 255) / 256, 256>>>(b2, temp);

    // big fused softmax + write: grid = 8 j2 x NBI i-blocks
    k_softmax_write<<<dim3(GROUPS, NBI), 256>>>(out);

    // if output is the whole tuple (w, mask), fill the mask tail
    long long extra = (long long)out_size - W_ELEMS;
    if (extra > 0) {
        k_detect_mask<<<1, 256>>>((const unsigned char*)mask);
        int nb = (int)((extra + 255) / 256);
        k_mask_tail<<<nb, 256>>>(out + W_ELEMS, mask, extra);
    }
}